// round 15
// baseline (speedup 1.0000x reference)
#include <cuda_runtime.h>
#include <cuda_fp16.h>
#include <math.h>
#include <stdint.h>

#define Nn 4096
#define Hh 4
#define NWORDS 128   // Nn/32

// ---------------- scratch (static device globals; no allocation) -------------
__device__ uint32_t g_mask[Nn * NWORDS];          // 2 MB packed adjacency
__device__ __half g_x16[Nn * 512];                // fp16 input features
__device__ __half g_W16[172032];                  // fp16 W1|W2|W3 (offsets below)
__device__ __half g_Wh16[Hh * Nn * 64];           // fp16 Wh
__device__ __half2 g_E1h[Hh * Nn];                // (e^f1, e^{0.2 f1}) fp16
__device__ __half2 g_E2h[Hh * Nn];                // (e^f2, e^{0.2 f2}) fp16
__device__ __half g_h1h[Nn * 256];
__device__ __half g_h2h[Nn * 128];
__device__ __half g_h3h[Nn * 64];

#define W2_OFF 131072   // 4*512*64
#define W3_OFF 163840   // +4*256*32

static __device__ __forceinline__ uint32_t smem_cast(const void* p) {
    return (uint32_t)__cvta_generic_to_shared(p);
}

static __device__ __forceinline__ void ldsm_x4(uint32_t* r, uint32_t addr) {
    asm volatile("ldmatrix.sync.aligned.m8n8.x4.shared.b16 {%0,%1,%2,%3}, [%4];"
                 : "=r"(r[0]), "=r"(r[1]), "=r"(r[2]), "=r"(r[3]) : "r"(addr));
}

static __device__ __forceinline__ void ldsm_x4t(uint32_t* r, uint32_t addr) {
    asm volatile("ldmatrix.sync.aligned.m8n8.x4.trans.shared.b16 {%0,%1,%2,%3}, [%4];"
                 : "=r"(r[0]), "=r"(r[1]), "=r"(r[2]), "=r"(r[3]) : "r"(addr));
}

static __device__ __forceinline__ void cp_async16(uint32_t dst, const void* src) {
    asm volatile("cp.async.ca.shared.global [%0], [%1], 16;" :: "r"(dst), "l"(src));
}
// L2-only variant: streamed data with no intra-CTA reuse (keeps L1 free)
static __device__ __forceinline__ void cp_async16_cg(uint32_t dst, const void* src) {
    asm volatile("cp.async.cg.shared.global [%0], [%1], 16;" :: "r"(dst), "l"(src));
}
static __device__ __forceinline__ void cp_commit() {
    asm volatile("cp.async.commit_group;");
}
static __device__ __forceinline__ void cp_wait0() {
    asm volatile("cp.async.wait_group 0;");
}

static __device__ __forceinline__ void mma_16816(float* acc, const uint32_t* a,
                                                 uint32_t b0, uint32_t b1) {
    asm volatile(
        "mma.sync.aligned.m16n8k16.row.col.f32.f16.f16.f32 "
        "{%0,%1,%2,%3}, {%4,%5,%6,%7}, {%8,%9}, {%0,%1,%2,%3};"
        : "+f"(acc[0]), "+f"(acc[1]), "+f"(acc[2]), "+f"(acc[3])
        : "r"(a[0]), "r"(a[1]), "r"(a[2]), "r"(a[3]), "r"(b0), "r"(b1));
}

// ---------------- pack adjacency into bitmask --------------------------------
__global__ void pack_mask_kernel(const int* __restrict__ adj) {
    int idx = blockIdx.x * blockDim.x + threadIdx.x;  // one thread per 32-bit word
    int i = idx >> 7;
    int w = idx & 127;
    const int4* p = reinterpret_cast<const int4*>(adj + (size_t)i * Nn + (w << 5));
    uint32_t m = 0u;
#pragma unroll
    for (int q = 0; q < 8; q++) {
        int4 v = p[q];
        if (v.x) m |= 1u << (q * 4 + 0);
        if (v.y) m |= 1u << (q * 4 + 1);
        if (v.z) m |= 1u << (q * 4 + 2);
        if (v.w) m |= 1u << (q * 4 + 3);
    }
    g_mask[idx] = m;
}

// ---------------- merged fp32 -> fp16 convert (x, W1, W2, W3) ----------------
#define X4 524288   // Nn*512/4
#define A4 32768    // 4*512*64/4
#define B4 8192     // 4*256*32/4
#define C4 2048     // 4*128*16/4
__global__ void cvt_all_kernel(const float* __restrict__ x,
                               const float* __restrict__ W1,
                               const float* __restrict__ W2,
                               const float* __restrict__ W3) {
    int i = blockIdx.x * 256 + threadIdx.x;
    const float* src;
    __half* dst;
    int off;
    if (i < X4) { src = x; dst = g_x16; off = i; }
    else if (i < X4 + A4) { src = W1; dst = g_W16; off = i - X4; }
    else if (i < X4 + A4 + B4) { src = W2; dst = g_W16 + W2_OFF; off = i - X4 - A4; }
    else if (i < X4 + A4 + B4 + C4) { src = W3; dst = g_W16 + W3_OFF; off = i - X4 - A4 - B4; }
    else return;
    float4 v = ((const float4*)src)[off];
    __half2 a = __floats2half2_rn(v.x, v.y);
    __half2 b = __floats2half2_rn(v.z, v.w);
    ((uint2*)dst)[off] = make_uint2(*(uint32_t*)&a, *(uint32_t*)&b);
}

// ------- tensor-core Wh = A @ W[h] + fused attention scalars (fe) ------------
template <int FIN, int O, int THREADS>
__global__ __launch_bounds__(THREADS) void gemm_mma_kernel(
    const __half* __restrict__ A,     // [Nn][FIN]
    const __half* __restrict__ Wb,    // [Hh][FIN][O] fp16
    const float* __restrict__ a) {    // [Hh][2*O]
    constexpr int KC = 64;
    constexpr int NCH = FIN / KC;
    constexpr int NWARPS = THREADS / 32;
    constexpr int NW_N = NWARPS / 4;
    constexpr int WN = O / NW_N;
    constexpr int NT = WN / 8;
    constexpr int SAS = KC + 8;
    constexpr int SBS = O + 8;
    constexpr int ASEG = 64 * KC / 8;
    constexpr int BSEG = KC * O / 8;

    __shared__ __align__(16) __half sA[2][64][SAS];
    __shared__ __align__(16) __half sB[2][KC][SBS];
    __shared__ float sF1[64][NW_N], sF2[64][NW_N];

    const int h = blockIdx.y;
    const int n0 = blockIdx.x * 64;
    const int t = threadIdx.x;
    const int lane = t & 31, wid = t >> 5;
    const int row0 = (wid / NW_N) * 16, col0 = (wid % NW_N) * WN;
    const int wn = wid % NW_N;

    const __half* Abase = A + (size_t)n0 * FIN;
    const __half* Bbase = Wb + (size_t)h * FIN * O;

    float acc[NT][4];
#pragma unroll
    for (int nt = 0; nt < NT; nt++)
#pragma unroll
        for (int q = 0; q < 4; q++) acc[nt][q] = 0.f;

    auto issue = [&](int c, int buf) {
#pragma unroll
        for (int v = 0; v < (ASEG + THREADS - 1) / THREADS; v++) {
            int i = t + v * THREADS;
            if (i < ASEG) {
                int row = i >> 3, off = (i & 7) * 8;
                cp_async16(smem_cast(&sA[buf][row][off]),
                           Abase + (size_t)row * FIN + c * KC + off);
            }
        }
#pragma unroll
        for (int v = 0; v < (BSEG + THREADS - 1) / THREADS; v++) {
            int i = t + v * THREADS;
            if (i < BSEG) {
                int kr = i / (O / 8), off = (i % (O / 8)) * 8;
                cp_async16(smem_cast(&sB[buf][kr][off]),
                           Bbase + (size_t)(c * KC + kr) * O + off);
            }
        }
        cp_commit();
    };

    issue(0, 0);
    for (int c = 0; c < NCH; c++) {
        const int buf = c & 1;
        cp_wait0();
        __syncthreads();
        if (c + 1 < NCH) issue(c + 1, buf ^ 1);
        uint32_t av[4][4], bfr[NT][8];
#pragma unroll
        for (int ks = 0; ks < 4; ks++)
            ldsm_x4(av[ks], smem_cast(&sA[buf][row0 + (lane & 15)]
                                         [ks * 16 + ((lane >> 4) & 1) * 8]));
#pragma unroll
        for (int nt = 0; nt < NT; nt++) {
            ldsm_x4t(bfr[nt], smem_cast(&sB[buf][lane][col0 + nt * 8]));
            ldsm_x4t(bfr[nt] + 4, smem_cast(&sB[buf][32 + lane][col0 + nt * 8]));
        }
#pragma unroll
        for (int ks = 0; ks < 4; ks++)
#pragma unroll
            for (int nt = 0; nt < NT; nt++)
                mma_16816(acc[nt], av[ks], bfr[nt][2 * ks], bfr[nt][2 * ks + 1]);
        __syncthreads();
    }

    // epilogue: store fp16 Wh + fused fe
    const float* avec = a + h * 2 * O;
    const int r = row0 + (lane >> 2);
    float f1a = 0.f, f2a = 0.f, f1b = 0.f, f2b = 0.f;
#pragma unroll
    for (int nt = 0; nt < NT; nt++) {
        int cb = col0 + nt * 8 + (lane & 3) * 2;
        __half2 lo = __floats2half2_rn(acc[nt][0], acc[nt][1]);
        __half2 hi = __floats2half2_rn(acc[nt][2], acc[nt][3]);
        *(__half2*)&g_Wh16[((size_t)h * Nn + n0 + r) * O + cb] = lo;
        *(__half2*)&g_Wh16[((size_t)h * Nn + n0 + r + 8) * O + cb] = hi;
        float a10 = avec[cb], a11 = avec[cb + 1];
        float a20 = avec[O + cb], a21 = avec[O + cb + 1];
        f1a += acc[nt][0] * a10 + acc[nt][1] * a11;
        f2a += acc[nt][0] * a20 + acc[nt][1] * a21;
        f1b += acc[nt][2] * a10 + acc[nt][3] * a11;
        f2b += acc[nt][2] * a20 + acc[nt][3] * a21;
    }
#pragma unroll
    for (int off = 1; off <= 2; off <<= 1) {
        f1a += __shfl_xor_sync(0xffffffffu, f1a, off);
        f2a += __shfl_xor_sync(0xffffffffu, f2a, off);
        f1b += __shfl_xor_sync(0xffffffffu, f1b, off);
        f2b += __shfl_xor_sync(0xffffffffu, f2b, off);
    }
    if ((lane & 3) == 0) {
        sF1[r][wn] = f1a; sF2[r][wn] = f2a;
        sF1[r + 8][wn] = f1b; sF2[r + 8][wn] = f2b;
    }
    __syncthreads();
    if (t < 64) {
        float f1 = 0.f, f2 = 0.f;
#pragma unroll
        for (int i = 0; i < NW_N; i++) { f1 += sF1[t][i]; f2 += sF2[t][i]; }
        int idx = h * Nn + n0 + t;
        g_E1h[idx] = __floats2half2_rn(expf(f1), expf(0.2f * f1));
        g_E2h[idx] = __floats2half2_rn(expf(f2), expf(0.2f * f2));
    }
}

// ---------------- fp16 tensor-core masked-softmax aggregation ----------------
// 64-row CTA tile, JJ=64 j-chunks, double-buffered smem, ONE barrier/chunk.
// E2/mask loads pipelined 2 chunks ahead (KPT==8 configs) with weight math 1
// ahead; consume loop keeps A-fragments per-ks to stay inside 64 regs.
template <int O, int THREADS>
__global__ __launch_bounds__(THREADS, 2) void agg_mma_kernel(__half* __restrict__ out,
                                                             int HO) {
    constexpr int JJ = 64;
    constexpr int NCH = Nn / JJ;
    constexpr int NWARPS = THREADS / 32;
    constexpr int NW_N = NWARPS / 4;
    constexpr int WN = O / NW_N;
    constexpr int NT = WN / 8;
    constexpr int SWS = JJ + 8;
    constexpr int SBS = O + 8;
    constexpr int TPR = THREADS / 64;
    constexpr int KPT = JJ / TPR;
    constexpr int NCP = JJ * O / 8;
    constexpr bool PIPE = (KPT == 8);
    constexpr int NSLOT = PIPE ? 2 : 1;

    __shared__ __align__(16) __half sW[2][64][SWS];
    __shared__ __align__(16) __half sWh[2][JJ][SBS];
    __shared__ float sZq[THREADS];
    __shared__ float sZ[64];

    const int h = blockIdx.y;
    const int n0 = blockIdx.x * 64;
    const int t = threadIdx.x;
    const int lane = t & 31, wid = t >> 5;
    const int row0 = (wid / NW_N) * 16, col0 = (wid % NW_N) * WN;

    const int rq = t / TPR, kq = t % TPR;
    const __half2 e1h = g_E1h[h * Nn + n0 + rq];
    const __half2* E2hH = g_E2h + h * Nn;
    const uint32_t* mrow = g_mask + (size_t)(n0 + rq) * NWORDS;

    const bool cpa = (t < NCP);
    const int cjj = t / (O / 8), coh = (t % (O / 8)) * 8;
    const __half* whsrc = g_Wh16 + ((size_t)h * Nn + cjj) * O + coh;

    float acc[NT][4];
#pragma unroll
    for (int nt = 0; nt < NT; nt++)
#pragma unroll
        for (int q = 0; q < 4; q++) acc[nt][q] = 0.f;
    float zloc = 0.f;

    uint32_t wreg[KPT / 2];
    uint4 ebuf[NSLOT][KPT / 4];
    uint2 mbuf[NSLOT];

    auto eload = [&](int c, int s) {
        mbuf[s] = *(const uint2*)(mrow + 2 * c);
        const int j0 = c * JJ + kq * KPT;
#pragma unroll
        for (int v = 0; v < KPT / 4; v++)
            ebuf[s][v] = *(const uint4*)(E2hH + j0 + v * 4);
    };
    auto wmath = [&](int s) {
        uint64_t m64 = ((uint64_t)mbuf[s].y << 32) | mbuf[s].x;
        uint32_t m = (uint32_t)(m64 >> (kq * KPT));
        const __half2* e2arr = (const __half2*)&ebuf[s][0];
#pragma unroll
        for (int i = 0; i < KPT / 2; i++) {
            __half2 pa = __hmul2(e1h, e2arr[2 * i]);
            __half2 pb = __hmul2(e1h, e2arr[2 * i + 1]);
            __half wa = __hmax(__low2half(pa), __high2half(pa));
            __half wb = __hmax(__low2half(pb), __high2half(pb));
            if (!((m >> (2 * i)) & 1u)) wa = __ushort_as_half(0);
            if (!((m >> (2 * i + 1)) & 1u)) wb = __ushort_as_half(0);
            __half2 hw = __halves2half2(wa, wb);
            wreg[i] = *(uint32_t*)&hw;
        }
    };
    auto issue_wh = [&](int c, int buf) {
        if (cpa)
            cp_async16_cg(smem_cast(&sWh[buf][cjj][coh]),
                          whsrc + (size_t)(c * JJ) * O);
        cp_commit();
    };

    eload(0, 0);
    if (PIPE) eload(1, 1);
    wmath(0);
    issue_wh(0, 0);

    for (int c = 0; c < NCH; c++) {
        const int buf = c & 1;
        // store weights(c), accumulate Z (half2 tree, then one convert)
#pragma unroll
        for (int s = 0; s < KPT / 8; s++)
            *(uint4*)&sW[buf][rq][kq * KPT + s * 8] =
                make_uint4(wreg[s * 4], wreg[s * 4 + 1],
                           wreg[s * 4 + 2], wreg[s * 4 + 3]);
        {
            __half2 z2 = *(__half2*)&wreg[0];
#pragma unroll
            for (int i = 1; i < KPT / 2; i++) z2 = __hadd2(z2, *(__half2*)&wreg[i]);
            float2 zf = __half22float2(z2);
            zloc += zf.x + zf.y;
        }
        cp_wait0();
        __syncthreads();
        if (PIPE) {
            if (c + 2 < NCH) eload(c + 2, c & 1);
            if (c + 1 < NCH) {
                wmath((c + 1) & 1);
                issue_wh(c + 1, buf ^ 1);
            }
        } else {
            if (c + 1 < NCH) {
                eload(c + 1, 0);
                wmath(0);
                issue_wh(c + 1, buf ^ 1);
            }
        }
        // consume chunk c: B fragments resident, A per-ks (low reg pressure)
        uint32_t bfr[NT][8];
#pragma unroll
        for (int nt = 0; nt < NT; nt++) {
            ldsm_x4t(bfr[nt], smem_cast(&sWh[buf][lane][col0 + nt * 8]));
            ldsm_x4t(bfr[nt] + 4, smem_cast(&sWh[buf][32 + lane][col0 + nt * 8]));
        }
#pragma unroll
        for (int ks = 0; ks < 4; ks++) {
            uint32_t a[4];
            ldsm_x4(a, smem_cast(&sW[buf][row0 + (lane & 15)]
                                    [ks * 16 + ((lane >> 4) & 1) * 8]));
#pragma unroll
            for (int nt = 0; nt < NT; nt++)
                mma_16816(acc[nt], a, bfr[nt][2 * ks], bfr[nt][2 * ks + 1]);
        }
    }
    sZq[t] = zloc;
    __syncthreads();
    if (t < 64) {
        float z = 0.f;
#pragma unroll
        for (int i = 0; i < TPR; i++) z += sZq[t * TPR + i];
        sZ[t] = z;
    }
    __syncthreads();
    {
        int r = row0 + (lane >> 2);
        float iz0 = 1.f / sZ[r];
        float iz1 = 1.f / sZ[r + 8];
#pragma unroll
        for (int nt = 0; nt < NT; nt++) {
            int cb = col0 + nt * 8 + (lane & 3) * 2;
            float v0 = acc[nt][0] * iz0;
            float v1 = acc[nt][1] * iz0;
            float v2 = acc[nt][2] * iz1;
            float v3 = acc[nt][3] * iz1;
            v0 = v0 > 0.f ? v0 : expm1f(v0);
            v1 = v1 > 0.f ? v1 : expm1f(v1);
            v2 = v2 > 0.f ? v2 : expm1f(v2);
            v3 = v3 > 0.f ? v3 : expm1f(v3);
            __half2 lo = __floats2half2_rn(v0, v1);
            __half2 hi = __floats2half2_rn(v2, v3);
            *(__half2*)&out[(size_t)(n0 + r) * HO + h * O + cb] = lo;
            *(__half2*)&out[(size_t)(n0 + r + 8) * HO + h * O + cb] = hi;
        }
    }
}

// ---------------- final linear + log_softmax ---------------------------------
__global__ void final_kernel(const float* __restrict__ Wlin,
                             const float* __restrict__ blin,
                             float* __restrict__ out) {
    int lane = threadIdx.x & 31;
    int n = (blockIdx.x * blockDim.x + threadIdx.x) >> 5;  // one warp per row
    const __half* hr = g_h3h + (size_t)n * 64;
    float v1 = -INFINITY;
    float a0 = blin[lane];
    float a1v = (lane < 8) ? blin[lane + 32] : 0.f;
#pragma unroll 16
    for (int k = 0; k < 64; k++) {
        float hv = __half2float(hr[k]);
        a0 += hv * Wlin[k * 40 + lane];
        if (lane < 8) a1v += hv * Wlin[k * 40 + lane + 32];
    }
    float v0 = a0;
    if (lane < 8) v1 = a1v;
    float m = fmaxf(v0, v1);
#pragma unroll
    for (int off = 16; off; off >>= 1) m = fmaxf(m, __shfl_xor_sync(0xffffffffu, m, off));
    float e = expf(v0 - m) + ((lane < 8) ? expf(v1 - m) : 0.f);
#pragma unroll
    for (int off = 16; off; off >>= 1) e += __shfl_xor_sync(0xffffffffu, e, off);
    float lse = m + logf(e);
    out[(size_t)n * 40 + lane] = v0 - lse;
    if (lane < 8) out[(size_t)n * 40 + lane + 32] = v1 - lse;
}

// ---------------- launch -----------------------------------------------------
extern "C" void kernel_launch(void* const* d_in, const int* in_sizes, int n_in,
                              void* d_out, int out_size) {
    const float* x    = (const float*)d_in[0];
    const int*   adj  = (const int*)d_in[1];
    const float* W1   = (const float*)d_in[2];
    const float* a1   = (const float*)d_in[3];
    const float* W2   = (const float*)d_in[4];
    const float* a2   = (const float*)d_in[5];
    const float* W3   = (const float*)d_in[6];
    const float* a3   = (const float*)d_in[7];
    const float* Wlin = (const float*)d_in[8];
    const float* blin = (const float*)d_in[9];
    float* out = (float*)d_out;

    __half *x16, *W16, *h1h, *h2h, *h3h;
    cudaGetSymbolAddress((void**)&x16, g_x16);
    cudaGetSymbolAddress((void**)&W16, g_W16);
    cudaGetSymbolAddress((void**)&h1h, g_h1h);
    cudaGetSymbolAddress((void**)&h2h, g_h2h);
    cudaGetSymbolAddress((void**)&h3h, g_h3h);

    pack_mask_kernel<<<(Nn * NWORDS) / 256, 256>>>(adj);
    cvt_all_kernel<<<(X4 + A4 + B4 + C4 + 255) / 256, 256>>>(x, W1, W2, W3);

    dim3 grid(Nn / 64, Hh);

    // stage 1: Fin=512, O=64
    gemm_mma_kernel<512, 64, 512><<<grid, 512>>>(x16, W16, a1);
    agg_mma_kernel<64, 512><<<grid, 512>>>(h1h, 256);

    // stage 2: Fin=256, O=32
    gemm_mma_kernel<256, 32, 512><<<grid, 512>>>(h1h, W16 + W2_OFF, a2);
    agg_mma_kernel<32, 512><<<grid, 512>>>(h2h, 128);

    // stage 3: Fin=128, O=16
    gemm_mma_kernel<128, 16, 256><<<grid, 256>>>(h2h, W16 + W3_OFF, a3);
    agg_mma_kernel<16, 256><<<grid, 256>>>(h3h, 64);

    final_kernel<<<(Nn * 32) / 256, 256>>>(Wlin, blin, out);
}

// round 17
// speedup vs baseline: 1.0923x; 1.0923x over previous
#include <cuda_runtime.h>
#include <cuda_fp16.h>
#include <math.h>
#include <stdint.h>

#define Nn 4096
#define Hh 4
#define NWORDS 128   // Nn/32

// ---------------- scratch (static device globals; no allocation) -------------
__device__ uint32_t g_mask[Nn * NWORDS];          // 2 MB packed adjacency
__device__ __half g_x16[Nn * 512];                // fp16 input features
__device__ __half g_W16[172032];                  // fp16 W1|W2|W3 (offsets below)
__device__ __half g_Wh16[Hh * Nn * 64];           // fp16 Wh
__device__ __half2 g_E1h[Hh * Nn];                // (e^f1, e^{0.2 f1}) fp16
__device__ __half2 g_E2h[Hh * Nn];                // (e^f2, e^{0.2 f2}) fp16
__device__ __half g_h1h[Nn * 256];
__device__ __half g_h2h[Nn * 128];
__device__ __half g_h3h[Nn * 64];

#define W2_OFF 131072   // 4*512*64
#define W3_OFF 163840   // +4*256*32

static __device__ __forceinline__ uint32_t smem_cast(const void* p) {
    return (uint32_t)__cvta_generic_to_shared(p);
}

static __device__ __forceinline__ void ldsm_x4(uint32_t* r, uint32_t addr) {
    asm volatile("ldmatrix.sync.aligned.m8n8.x4.shared.b16 {%0,%1,%2,%3}, [%4];"
                 : "=r"(r[0]), "=r"(r[1]), "=r"(r[2]), "=r"(r[3]) : "r"(addr));
}

static __device__ __forceinline__ void ldsm_x4t(uint32_t* r, uint32_t addr) {
    asm volatile("ldmatrix.sync.aligned.m8n8.x4.trans.shared.b16 {%0,%1,%2,%3}, [%4];"
                 : "=r"(r[0]), "=r"(r[1]), "=r"(r[2]), "=r"(r[3]) : "r"(addr));
}

static __device__ __forceinline__ void cp_async16(uint32_t dst, const void* src) {
    asm volatile("cp.async.ca.shared.global [%0], [%1], 16;" :: "r"(dst), "l"(src));
}
static __device__ __forceinline__ void cp_commit() {
    asm volatile("cp.async.commit_group;");
}
static __device__ __forceinline__ void cp_wait0() {
    asm volatile("cp.async.wait_group 0;");
}

static __device__ __forceinline__ void mma_16816(float* acc, const uint32_t* a,
                                                 uint32_t b0, uint32_t b1) {
    asm volatile(
        "mma.sync.aligned.m16n8k16.row.col.f32.f16.f16.f32 "
        "{%0,%1,%2,%3}, {%4,%5,%6,%7}, {%8,%9}, {%0,%1,%2,%3};"
        : "+f"(acc[0]), "+f"(acc[1]), "+f"(acc[2]), "+f"(acc[3])
        : "r"(a[0]), "r"(a[1]), "r"(a[2]), "r"(a[3]), "r"(b0), "r"(b1));
}

// ---------------- pack adjacency into bitmask --------------------------------
__global__ void pack_mask_kernel(const int* __restrict__ adj) {
    int idx = blockIdx.x * blockDim.x + threadIdx.x;  // one thread per 32-bit word
    int i = idx >> 7;
    int w = idx & 127;
    const int4* p = reinterpret_cast<const int4*>(adj + (size_t)i * Nn + (w << 5));
    uint32_t m = 0u;
#pragma unroll
    for (int q = 0; q < 8; q++) {
        int4 v = p[q];
        if (v.x) m |= 1u << (q * 4 + 0);
        if (v.y) m |= 1u << (q * 4 + 1);
        if (v.z) m |= 1u << (q * 4 + 2);
        if (v.w) m |= 1u << (q * 4 + 3);
    }
    g_mask[idx] = m;
}

// ---------------- merged fp32 -> fp16 convert (x, W1, W2, W3) ----------------
#define X4 524288   // Nn*512/4
#define A4 32768    // 4*512*64/4
#define B4 8192     // 4*256*32/4
#define C4 2048     // 4*128*16/4
__global__ void cvt_all_kernel(const float* __restrict__ x,
                               const float* __restrict__ W1,
                               const float* __restrict__ W2,
                               const float* __restrict__ W3) {
    int i = blockIdx.x * 256 + threadIdx.x;
    const float* src;
    __half* dst;
    int off;
    if (i < X4) { src = x; dst = g_x16; off = i; }
    else if (i < X4 + A4) { src = W1; dst = g_W16; off = i - X4; }
    else if (i < X4 + A4 + B4) { src = W2; dst = g_W16 + W2_OFF; off = i - X4 - A4; }
    else if (i < X4 + A4 + B4 + C4) { src = W3; dst = g_W16 + W3_OFF; off = i - X4 - A4 - B4; }
    else return;
    float4 v = ((const float4*)src)[off];
    __half2 a = __floats2half2_rn(v.x, v.y);
    __half2 b = __floats2half2_rn(v.z, v.w);
    ((uint2*)dst)[off] = make_uint2(*(uint32_t*)&a, *(uint32_t*)&b);
}

// ------- tensor-core Wh = A @ W[h] + fused attention scalars (fe) ------------
template <int FIN, int O, int THREADS>
__global__ __launch_bounds__(THREADS) void gemm_mma_kernel(
    const __half* __restrict__ A,     // [Nn][FIN]
    const __half* __restrict__ Wb,    // [Hh][FIN][O] fp16
    const float* __restrict__ a) {    // [Hh][2*O]
    constexpr int KC = 64;
    constexpr int NCH = FIN / KC;
    constexpr int NWARPS = THREADS / 32;
    constexpr int NW_N = NWARPS / 4;
    constexpr int WN = O / NW_N;
    constexpr int NT = WN / 8;
    constexpr int SAS = KC + 8;
    constexpr int SBS = O + 8;
    constexpr int ASEG = 64 * KC / 8;
    constexpr int BSEG = KC * O / 8;

    __shared__ __align__(16) __half sA[2][64][SAS];
    __shared__ __align__(16) __half sB[2][KC][SBS];
    __shared__ float sF1[64][NW_N], sF2[64][NW_N];

    const int h = blockIdx.y;
    const int n0 = blockIdx.x * 64;
    const int t = threadIdx.x;
    const int lane = t & 31, wid = t >> 5;
    const int row0 = (wid / NW_N) * 16, col0 = (wid % NW_N) * WN;
    const int wn = wid % NW_N;

    const __half* Abase = A + (size_t)n0 * FIN;
    const __half* Bbase = Wb + (size_t)h * FIN * O;

    float acc[NT][4];
#pragma unroll
    for (int nt = 0; nt < NT; nt++)
#pragma unroll
        for (int q = 0; q < 4; q++) acc[nt][q] = 0.f;

    auto issue = [&](int c, int buf) {
#pragma unroll
        for (int v = 0; v < (ASEG + THREADS - 1) / THREADS; v++) {
            int i = t + v * THREADS;
            if (i < ASEG) {
                int row = i >> 3, off = (i & 7) * 8;
                cp_async16(smem_cast(&sA[buf][row][off]),
                           Abase + (size_t)row * FIN + c * KC + off);
            }
        }
#pragma unroll
        for (int v = 0; v < (BSEG + THREADS - 1) / THREADS; v++) {
            int i = t + v * THREADS;
            if (i < BSEG) {
                int kr = i / (O / 8), off = (i % (O / 8)) * 8;
                cp_async16(smem_cast(&sB[buf][kr][off]),
                           Bbase + (size_t)(c * KC + kr) * O + off);
            }
        }
        cp_commit();
    };

    issue(0, 0);
    for (int c = 0; c < NCH; c++) {
        const int buf = c & 1;
        cp_wait0();
        __syncthreads();
        if (c + 1 < NCH) issue(c + 1, buf ^ 1);
        uint32_t av[4][4], bfr[NT][8];
#pragma unroll
        for (int ks = 0; ks < 4; ks++)
            ldsm_x4(av[ks], smem_cast(&sA[buf][row0 + (lane & 15)]
                                         [ks * 16 + ((lane >> 4) & 1) * 8]));
#pragma unroll
        for (int nt = 0; nt < NT; nt++) {
            ldsm_x4t(bfr[nt], smem_cast(&sB[buf][lane][col0 + nt * 8]));
            ldsm_x4t(bfr[nt] + 4, smem_cast(&sB[buf][32 + lane][col0 + nt * 8]));
        }
#pragma unroll
        for (int ks = 0; ks < 4; ks++)
#pragma unroll
            for (int nt = 0; nt < NT; nt++)
                mma_16816(acc[nt], av[ks], bfr[nt][2 * ks], bfr[nt][2 * ks + 1]);
        __syncthreads();
    }

    // epilogue: store fp16 Wh + fused fe
    const float* avec = a + h * 2 * O;
    const int r = row0 + (lane >> 2);
    float f1a = 0.f, f2a = 0.f, f1b = 0.f, f2b = 0.f;
#pragma unroll
    for (int nt = 0; nt < NT; nt++) {
        int cb = col0 + nt * 8 + (lane & 3) * 2;
        __half2 lo = __floats2half2_rn(acc[nt][0], acc[nt][1]);
        __half2 hi = __floats2half2_rn(acc[nt][2], acc[nt][3]);
        *(__half2*)&g_Wh16[((size_t)h * Nn + n0 + r) * O + cb] = lo;
        *(__half2*)&g_Wh16[((size_t)h * Nn + n0 + r + 8) * O + cb] = hi;
        float a10 = avec[cb], a11 = avec[cb + 1];
        float a20 = avec[O + cb], a21 = avec[O + cb + 1];
        f1a += acc[nt][0] * a10 + acc[nt][1] * a11;
        f2a += acc[nt][0] * a20 + acc[nt][1] * a21;
        f1b += acc[nt][2] * a10 + acc[nt][3] * a11;
        f2b += acc[nt][2] * a20 + acc[nt][3] * a21;
    }
#pragma unroll
    for (int off = 1; off <= 2; off <<= 1) {
        f1a += __shfl_xor_sync(0xffffffffu, f1a, off);
        f2a += __shfl_xor_sync(0xffffffffu, f2a, off);
        f1b += __shfl_xor_sync(0xffffffffu, f1b, off);
        f2b += __shfl_xor_sync(0xffffffffu, f2b, off);
    }
    if ((lane & 3) == 0) {
        sF1[r][wn] = f1a; sF2[r][wn] = f2a;
        sF1[r + 8][wn] = f1b; sF2[r + 8][wn] = f2b;
    }
    __syncthreads();
    if (t < 64) {
        float f1 = 0.f, f2 = 0.f;
#pragma unroll
        for (int i = 0; i < NW_N; i++) { f1 += sF1[t][i]; f2 += sF2[t][i]; }
        int idx = h * Nn + n0 + t;
        g_E1h[idx] = __floats2half2_rn(expf(f1), expf(0.2f * f1));
        g_E2h[idx] = __floats2half2_rn(expf(f2), expf(0.2f * f2));
    }
}

// ---------------- fp16 tensor-core masked-softmax aggregation ----------------
// R14 structure (64-row tile, JJ=64 chunks, double-buffered, ONE barrier/chunk)
// + E2 staged through smem by the same cp.async pipeline: issue_wh(c) copies
// E2(c+1) into sE2[buf], so produce_w reads LDS instead of exposed LDGs.
template <int O, int THREADS>
__global__ __launch_bounds__(THREADS, 2) void agg_mma_kernel(__half* __restrict__ out,
                                                             int HO) {
    constexpr int JJ = 64;
    constexpr int NCH = Nn / JJ;
    constexpr int NWARPS = THREADS / 32;
    constexpr int NW_N = NWARPS / 4;
    constexpr int WN = O / NW_N;
    constexpr int NT = WN / 8;
    constexpr int SWS = JJ + 8;
    constexpr int SBS = O + 8;
    constexpr int TPR = THREADS / 64;
    constexpr int KPT = JJ / TPR;
    constexpr int NCP = JJ * O / 8;

    __shared__ __align__(16) __half sW[2][64][SWS];
    __shared__ __align__(16) __half sWh[2][JJ][SBS];
    __shared__ __align__(16) __half2 sE2[2][JJ];
    __shared__ float sZq[THREADS];
    __shared__ float sZ[64];

    const int h = blockIdx.y;
    const int n0 = blockIdx.x * 64;
    const int t = threadIdx.x;
    const int lane = t & 31, wid = t >> 5;
    const int row0 = (wid / NW_N) * 16, col0 = (wid % NW_N) * WN;

    const int rq = t / TPR, kq = t % TPR;
    const __half2 e1h = g_E1h[h * Nn + n0 + rq];
    const __half2* E2hH = g_E2h + h * Nn;
    const uint32_t* mrow = g_mask + (size_t)(n0 + rq) * NWORDS;

    const bool cpa = (t < NCP);
    const int cjj = t / (O / 8), coh = (t % (O / 8)) * 8;
    const __half* whsrc = g_Wh16 + ((size_t)h * Nn + cjj) * O + coh;

    float acc[NT][4];
#pragma unroll
    for (int nt = 0; nt < NT; nt++)
#pragma unroll
        for (int q = 0; q < 4; q++) acc[nt][q] = 0.f;
    float zloc = 0.f;

    uint32_t wreg[KPT / 2];
    uint32_t mbuf[4];

    // e2src: base of the 64-half2 chunk (global for chunk 0, smem afterwards)
    auto produce_w = [&](int c, const __half2* e2src) {
        if ((c & 1) == 0) {
            uint4 mv = *(const uint4*)(mrow + 2 * c);
            mbuf[0] = mv.x; mbuf[1] = mv.y; mbuf[2] = mv.z; mbuf[3] = mv.w;
        }
        uint64_t m64 = ((uint64_t)mbuf[(c & 1) * 2 + 1] << 32) | mbuf[(c & 1) * 2];
        uint32_t m = (uint32_t)(m64 >> (kq * KPT));
        uint4 ebuf[KPT / 4];
#pragma unroll
        for (int v = 0; v < KPT / 4; v++)
            ebuf[v] = *(const uint4*)(e2src + kq * KPT + v * 4);
        const __half2* e2arr = (const __half2*)ebuf;
#pragma unroll
        for (int i = 0; i < KPT / 2; i++) {
            __half2 pa = __hmul2(e1h, e2arr[2 * i]);
            __half2 pb = __hmul2(e1h, e2arr[2 * i + 1]);
            __half wa = __hmax(__low2half(pa), __high2half(pa));
            __half wb = __hmax(__low2half(pb), __high2half(pb));
            if (!((m >> (2 * i)) & 1u)) wa = __ushort_as_half(0);
            if (!((m >> (2 * i + 1)) & 1u)) wb = __ushort_as_half(0);
            __half2 hw = __halves2half2(wa, wb);
            wreg[i] = *(uint32_t*)&hw;
        }
    };
    // copies Wh(c) into sWh[buf] and E2(c+1) into sE2[buf]
    auto issue_wh = [&](int c, int buf) {
        if (cpa)
            cp_async16(smem_cast(&sWh[buf][cjj][coh]),
                       whsrc + (size_t)(c * JJ) * O);
        if (t < JJ / 4) {
            int cc = (c + 1 < NCH) ? c + 1 : 0;
            cp_async16(smem_cast(&sE2[buf][t * 4]), E2hH + cc * JJ + t * 4);
        }
        cp_commit();
    };

    produce_w(0, E2hH);   // chunk 0: E2 direct from global (once)
    issue_wh(0, 0);

    for (int c = 0; c < NCH; c++) {
        const int buf = c & 1;
#pragma unroll
        for (int s = 0; s < KPT / 8; s++)
            *(uint4*)&sW[buf][rq][kq * KPT + s * 8] =
                make_uint4(wreg[s * 4], wreg[s * 4 + 1],
                           wreg[s * 4 + 2], wreg[s * 4 + 3]);
#pragma unroll
        for (int i = 0; i < KPT / 2; i++) {
            float2 f = __half22float2(*(__half2*)&wreg[i]);
            zloc += f.x + f.y;
        }
        cp_wait0();
        __syncthreads();
        if (c + 1 < NCH) {
            produce_w(c + 1, sE2[buf]);   // E2(c+1) landed with this buf's copy
            issue_wh(c + 1, buf ^ 1);
        }
        uint32_t a[4][4], bfr[NT][8];
#pragma unroll
        for (int ks = 0; ks < 4; ks++)
            ldsm_x4(a[ks], smem_cast(&sW[buf][row0 + (lane & 15)]
                                        [ks * 16 + ((lane >> 4) & 1) * 8]));
#pragma unroll
        for (int nt = 0; nt < NT; nt++) {
            ldsm_x4t(bfr[nt], smem_cast(&sWh[buf][lane][col0 + nt * 8]));
            ldsm_x4t(bfr[nt] + 4, smem_cast(&sWh[buf][32 + lane][col0 + nt * 8]));
        }
#pragma unroll
        for (int ks = 0; ks < 4; ks++)
#pragma unroll
            for (int nt = 0; nt < NT; nt++)
                mma_16816(acc[nt], a[ks], bfr[nt][2 * ks], bfr[nt][2 * ks + 1]);
    }
    sZq[t] = zloc;
    __syncthreads();
    if (t < 64) {
        float z = 0.f;
#pragma unroll
        for (int i = 0; i < TPR; i++) z += sZq[t * TPR + i];
        sZ[t] = z;
    }
    __syncthreads();
    {
        int r = row0 + (lane >> 2);
        float iz0 = 1.f / sZ[r];
        float iz1 = 1.f / sZ[r + 8];
#pragma unroll
        for (int nt = 0; nt < NT; nt++) {
            int cb = col0 + nt * 8 + (lane & 3) * 2;
            float v0 = acc[nt][0] * iz0;
            float v1 = acc[nt][1] * iz0;
            float v2 = acc[nt][2] * iz1;
            float v3 = acc[nt][3] * iz1;
            v0 = v0 > 0.f ? v0 : expm1f(v0);
            v1 = v1 > 0.f ? v1 : expm1f(v1);
            v2 = v2 > 0.f ? v2 : expm1f(v2);
            v3 = v3 > 0.f ? v3 : expm1f(v3);
            __half2 lo = __floats2half2_rn(v0, v1);
            __half2 hi = __floats2half2_rn(v2, v3);
            *(__half2*)&out[(size_t)(n0 + r) * HO + h * O + cb] = lo;
            *(__half2*)&out[(size_t)(n0 + r + 8) * HO + h * O + cb] = hi;
        }
    }
}

// ---------------- final linear + log_softmax ---------------------------------
__global__ void final_kernel(const float* __restrict__ Wlin,
                             const float* __restrict__ blin,
                             float* __restrict__ out) {
    int lane = threadIdx.x & 31;
    int n = (blockIdx.x * blockDim.x + threadIdx.x) >> 5;  // one warp per row
    const __half* hr = g_h3h + (size_t)n * 64;
    float v1 = -INFINITY;
    float a0 = blin[lane];
    float a1v = (lane < 8) ? blin[lane + 32] : 0.f;
#pragma unroll 16
    for (int k = 0; k < 64; k++) {
        float hv = __half2float(hr[k]);
        a0 += hv * Wlin[k * 40 + lane];
        if (lane < 8) a1v += hv * Wlin[k * 40 + lane + 32];
    }
    float v0 = a0;
    if (lane < 8) v1 = a1v;
    float m = fmaxf(v0, v1);
#pragma unroll
    for (int off = 16; off; off >>= 1) m = fmaxf(m, __shfl_xor_sync(0xffffffffu, m, off));
    float e = expf(v0 - m) + ((lane < 8) ? expf(v1 - m) : 0.f);
#pragma unroll
    for (int off = 16; off; off >>= 1) e += __shfl_xor_sync(0xffffffffu, e, off);
    float lse = m + logf(e);
    out[(size_t)n * 40 + lane] = v0 - lse;
    if (lane < 8) out[(size_t)n * 40 + lane + 32] = v1 - lse;
}

// ---------------- launch -----------------------------------------------------
extern "C" void kernel_launch(void* const* d_in, const int* in_sizes, int n_in,
                              void* d_out, int out_size) {
    const float* x    = (const float*)d_in[0];
    const int*   adj  = (const int*)d_in[1];
    const float* W1   = (const float*)d_in[2];
    const float* a1   = (const float*)d_in[3];
    const float* W2   = (const float*)d_in[4];
    const float* a2   = (const float*)d_in[5];
    const float* W3   = (const float*)d_in[6];
    const float* a3   = (const float*)d_in[7];
    const float* Wlin = (const float*)d_in[8];
    const float* blin = (const float*)d_in[9];
    float* out = (float*)d_out;

    __half *x16, *W16, *h1h, *h2h, *h3h;
    cudaGetSymbolAddress((void**)&x16, g_x16);
    cudaGetSymbolAddress((void**)&W16, g_W16);
    cudaGetSymbolAddress((void**)&h1h, g_h1h);
    cudaGetSymbolAddress((void**)&h2h, g_h2h);
    cudaGetSymbolAddress((void**)&h3h, g_h3h);

    pack_mask_kernel<<<(Nn * NWORDS) / 256, 256>>>(adj);
    cvt_all_kernel<<<(X4 + A4 + B4 + C4 + 255) / 256, 256>>>(x, W1, W2, W3);

    dim3 grid(Nn / 64, Hh);

    // stage 1: Fin=512, O=64
    gemm_mma_kernel<512, 64, 512><<<grid, 512>>>(x16, W16, a1);
    agg_mma_kernel<64, 512><<<grid, 512>>>(h1h, 256);

    // stage 2: Fin=256, O=32
    gemm_mma_kernel<256, 32, 512><<<grid, 512>>>(h1h, W16 + W2_OFF, a2);
    agg_mma_kernel<32, 512><<<grid, 512>>>(h2h, 128);

    // stage 3: Fin=128, O=16
    gemm_mma_kernel<128, 16, 256><<<grid, 256>>>(h2h, W16 + W3_OFF, a3);
    agg_mma_kernel<16, 256><<<grid, 256>>>(h3h, 64);

    final_kernel<<<(Nn * 32) / 256, 256>>>(Wlin, blin, out);
}